// round 1
// baseline (speedup 1.0000x reference)
#include <cuda_runtime.h>
#include <math.h>

#define SEQL 2048
#define HID  2048
#define NH   32
#define NKV  8
#define HD   64

// Scratch (no allocations allowed)
__device__ float g_q[SEQL * NH * HD];     // [s][h*64+d]  16MB
__device__ float g_k[SEQL * NKV * HD];    // [s][kh*64+d]  4MB
__device__ float g_v[SEQL * NKV * HD];    //               4MB
__device__ float g_attn[SEQL * NH * HD];  // [s][h*64+d]  16MB

// ---------------------------------------------------------------------------
// SGEMM: C[M,N] = A[M,K] @ B[K,N], row-major, all dims multiples of tile sizes.
// 128x128 block tile, BK=16, 256 threads, 8x8 per thread.
// ---------------------------------------------------------------------------
__global__ __launch_bounds__(256) void sgemm128(const float* __restrict__ A,
                                                const float* __restrict__ B,
                                                float* __restrict__ C,
                                                int N, int K) {
    __shared__ float As[16][128];   // [k][m]
    __shared__ float Bs[16][128];   // [k][n]

    const int bm = blockIdx.y;
    const int bn = blockIdx.x;
    const int tid = threadIdx.x;
    const int ty = tid >> 4;        // 0..15
    const int tx = tid & 15;        // 0..15

    const float* Ab = A + (size_t)bm * 128 * K;
    const float* Bb = B + (size_t)bn * 128;

    float acc[8][8];
#pragma unroll
    for (int i = 0; i < 8; i++)
#pragma unroll
        for (int j = 0; j < 8; j++) acc[i][j] = 0.f;

    for (int k0 = 0; k0 < K; k0 += 16) {
#pragma unroll
        for (int r = 0; r < 2; r++) {
            int f = r * 256 + tid;          // 0..511
            // A tile: 128 rows x 4 float4
            int arow = f >> 2, ac4 = f & 3;
            float4 va = *(const float4*)(Ab + (size_t)arow * K + k0 + ac4 * 4);
            As[ac4 * 4 + 0][arow] = va.x;
            As[ac4 * 4 + 1][arow] = va.y;
            As[ac4 * 4 + 2][arow] = va.z;
            As[ac4 * 4 + 3][arow] = va.w;
            // B tile: 16 rows x 32 float4
            int brow = f >> 5, bc4 = f & 31;
            float4 vb = *(const float4*)(Bb + (size_t)(k0 + brow) * N + bc4 * 4);
            *(float4*)&Bs[brow][bc4 * 4] = vb;
        }
        __syncthreads();

#pragma unroll
        for (int kk = 0; kk < 16; kk++) {
            float a[8], b[8];
            *(float4*)&a[0] = *(const float4*)&As[kk][ty * 8];
            *(float4*)&a[4] = *(const float4*)&As[kk][ty * 8 + 4];
            *(float4*)&b[0] = *(const float4*)&Bs[kk][tx * 8];
            *(float4*)&b[4] = *(const float4*)&Bs[kk][tx * 8 + 4];
#pragma unroll
            for (int i = 0; i < 8; i++)
#pragma unroll
                for (int j = 0; j < 8; j++) acc[i][j] = fmaf(a[i], b[j], acc[i][j]);
        }
        __syncthreads();
    }

#pragma unroll
    for (int i = 0; i < 8; i++) {
        float* Crow = C + (size_t)(bm * 128 + ty * 8 + i) * N + bn * 128 + tx * 8;
        *(float4*)&Crow[0] = make_float4(acc[i][0], acc[i][1], acc[i][2], acc[i][3]);
        *(float4*)&Crow[4] = make_float4(acc[i][4], acc[i][5], acc[i][6], acc[i][7]);
    }
}

// ---------------------------------------------------------------------------
// RoPE (replicates the reference exactly):
//   out[d]   = x[d]*cos(t*f[d mod 32]) + rot[d]*sin(t*f[d mod 32])
//   rot[2i]  = -x[2i+1], rot[2i+1] = x[2i]
//   f[j] = theta^(-j/32)
// ---------------------------------------------------------------------------
__global__ void rope_kernel(float* __restrict__ x, int nheads) {
    int p = blockIdx.x * blockDim.x + threadIdx.x;
    int total = SEQL * nheads * (HD / 2);
    if (p >= total) return;
    int i = p & 31;                    // pair index 0..31
    int h = (p >> 5) % nheads;
    int s = p / (nheads * 32);

    float* row = x + (size_t)s * nheads * HD + h * HD;
    int d0 = 2 * i, d1 = 2 * i + 1;
    float x0 = row[d0], x1 = row[d1];
    int j0 = d0 & 31, j1 = d1 & 31;

    const float LOGT = 13.122363377404328f;  // ln(500000)
    float f0 = expf(-(float)j0 * (LOGT / 32.f));
    float f1 = expf(-(float)j1 * (LOGT / 32.f));
    float t = (float)s;
    float s0, c0, s1, c1;
    sincosf(t * f0, &s0, &c0);
    sincosf(t * f1, &s1, &c1);
    row[d0] = x0 * c0 - x1 * s0;
    row[d1] = x1 * c1 + x0 * s1;
}

// ---------------------------------------------------------------------------
// Flash attention, fp32 SIMT. grid = (SEQ/64, NH), 256 threads.
// 64x64 tiles, online softmax, causal. P reuses the K smem tile (48KB total).
// ---------------------------------------------------------------------------
__global__ __launch_bounds__(256) void attn_kernel(const float* __restrict__ Q,
                                                   const float* __restrict__ K,
                                                   const float* __restrict__ V,
                                                   float* __restrict__ O) {
    __shared__ float Qs[64][64];    // [d][m] (transposed)
    __shared__ float KPs[64][64];   // phase 1: K transposed [d][n]; phase 2: P transposed [c][m]
    __shared__ float Vs[64][64];    // [c][dv]

    const int h = blockIdx.y;
    const int qb = blockIdx.x;
    const int kvh = h >> 2;         // 32 heads -> 8 kv heads (groups of 4)
    const int tid = threadIdx.x;
    const int ty = tid >> 4, tx = tid & 15;

    // Load Q tile transposed: 64 rows x 16 float4
#pragma unroll
    for (int r = 0; r < 4; r++) {
        int f = r * 256 + tid;           // 0..1023
        int m = f >> 4, c4 = f & 15;
        float4 v4 = *(const float4*)(Q + (size_t)(qb * 64 + m) * (NH * HD) + h * HD + c4 * 4);
        Qs[c4 * 4 + 0][m] = v4.x;
        Qs[c4 * 4 + 1][m] = v4.y;
        Qs[c4 * 4 + 2][m] = v4.z;
        Qs[c4 * 4 + 3][m] = v4.w;
    }

    float mi[4], li[4], acc[4][4];
#pragma unroll
    for (int i = 0; i < 4; i++) {
        mi[i] = -1e30f; li[i] = 0.f;
#pragma unroll
        for (int j = 0; j < 4; j++) acc[i][j] = 0.f;
    }

    for (int jb = 0; jb <= qb; jb++) {
        __syncthreads();   // previous iter's P/V readers done (and Q tile ready on iter 0)

        // Load K (transposed) and V tiles
#pragma unroll
        for (int r = 0; r < 4; r++) {
            int f = r * 256 + tid;
            int n = f >> 4, c4 = f & 15;
            size_t base = (size_t)(jb * 64 + n) * (NKV * HD) + kvh * HD + c4 * 4;
            float4 kv = *(const float4*)(K + base);
            KPs[c4 * 4 + 0][n] = kv.x;
            KPs[c4 * 4 + 1][n] = kv.y;
            KPs[c4 * 4 + 2][n] = kv.z;
            KPs[c4 * 4 + 3][n] = kv.w;
            *(float4*)&Vs[n][c4 * 4] = *(const float4*)(V + base);
        }
        __syncthreads();

        // S = Q K^T  (4x4 per thread)
        float s[4][4];
#pragma unroll
        for (int i = 0; i < 4; i++)
#pragma unroll
            for (int j = 0; j < 4; j++) s[i][j] = 0.f;
#pragma unroll
        for (int d = 0; d < 64; d++) {
            float a[4], b[4];
            *(float4*)a = *(const float4*)&Qs[d][ty * 4];
            *(float4*)b = *(const float4*)&KPs[d][tx * 4];
#pragma unroll
            for (int i = 0; i < 4; i++)
#pragma unroll
                for (int j = 0; j < 4; j++) s[i][j] = fmaf(a[i], b[j], s[i][j]);
        }
        __syncthreads();   // everyone done reading K before P overwrites it

        // scale + causal mask (-1e9, matching reference; underflows to exact 0)
        const float scale = 0.125f;
        int row0 = qb * 64 + ty * 4;
        int col0 = jb * 64 + tx * 4;
#pragma unroll
        for (int i = 0; i < 4; i++)
#pragma unroll
            for (int j = 0; j < 4; j++)
                s[i][j] = s[i][j] * scale + ((col0 + j > row0 + i) ? -1e9f : 0.f);

        // online softmax (row stats shared by 16 lanes via shuffles)
#pragma unroll
        for (int i = 0; i < 4; i++) {
            float rm = fmaxf(fmaxf(s[i][0], s[i][1]), fmaxf(s[i][2], s[i][3]));
#pragma unroll
            for (int off = 8; off; off >>= 1)
                rm = fmaxf(rm, __shfl_xor_sync(0xffffffffu, rm, off));
            float nm = fmaxf(mi[i], rm);
            float alpha = expf(mi[i] - nm);
            mi[i] = nm;
            float rs = 0.f;
#pragma unroll
            for (int j = 0; j < 4; j++) { s[i][j] = expf(s[i][j] - nm); rs += s[i][j]; }
#pragma unroll
            for (int off = 8; off; off >>= 1)
                rs += __shfl_xor_sync(0xffffffffu, rs, off);
            li[i] = li[i] * alpha + rs;
#pragma unroll
            for (int j = 0; j < 4; j++) acc[i][j] *= alpha;
        }

        // store P transposed into the K tile: KPs[c][m]
#pragma unroll
        for (int j = 0; j < 4; j++)
            *(float4*)&KPs[tx * 4 + j][ty * 4] =
                make_float4(s[0][j], s[1][j], s[2][j], s[3][j]);
        __syncthreads();

        // O += P V
#pragma unroll
        for (int c = 0; c < 64; c++) {
            float a[4], b[4];
            *(float4*)a = *(const float4*)&KPs[c][ty * 4];
            *(float4*)b = *(const float4*)&Vs[c][tx * 4];
#pragma unroll
            for (int i = 0; i < 4; i++)
#pragma unroll
                for (int j = 0; j < 4; j++) acc[i][j] = fmaf(a[i], b[j], acc[i][j]);
        }
    }

    // epilogue: normalize and store [s][h*64+d]
#pragma unroll
    for (int i = 0; i < 4; i++) {
        float inv = 1.0f / li[i];
        *(float4*)(O + (size_t)(qb * 64 + ty * 4 + i) * (NH * HD) + h * HD + tx * 4) =
            make_float4(acc[i][0] * inv, acc[i][1] * inv, acc[i][2] * inv, acc[i][3] * inv);
    }
}

// ---------------------------------------------------------------------------
extern "C" void kernel_launch(void* const* d_in, const int* in_sizes, int n_in,
                              void* d_out, int out_size) {
    const float* hidden = (const float*)d_in[0];
    // d_in[1] = attention_mask: exact causal 0/-1e9 mask, applied analytically.
    const float* Wq = (const float*)d_in[2];
    const float* Wk = (const float*)d_in[3];
    const float* Wv = (const float*)d_in[4];
    const float* Wo = (const float*)d_in[5];
    float* out = (float*)d_out;

    float *qp, *kp, *vp, *ap;
    cudaGetSymbolAddress((void**)&qp, g_q);
    cudaGetSymbolAddress((void**)&kp, g_k);
    cudaGetSymbolAddress((void**)&vp, g_v);
    cudaGetSymbolAddress((void**)&ap, g_attn);

    // 1) QKV projections
    sgemm128<<<dim3(NH * HD / 128, SEQL / 128), 256>>>(hidden, Wq, qp, NH * HD, HID);
    sgemm128<<<dim3(NKV * HD / 128, SEQL / 128), 256>>>(hidden, Wk, kp, NKV * HD, HID);
    sgemm128<<<dim3(NKV * HD / 128, SEQL / 128), 256>>>(hidden, Wv, vp, NKV * HD, HID);

    // 2) RoPE on q and k
    {
        int tq = SEQL * NH * (HD / 2);
        rope_kernel<<<(tq + 255) / 256, 256>>>(qp, NH);
        int tk = SEQL * NKV * (HD / 2);
        rope_kernel<<<(tk + 255) / 256, 256>>>(kp, NKV);
    }

    // 3) causal GQA flash attention
    attn_kernel<<<dim3(SEQL / 64, NH), 256>>>(qp, kp, vp, ap);

    // 4) output projection
    sgemm128<<<dim3(HID / 128, SEQL / 128), 256>>>(ap, Wo, out, HID, HID);
}

// round 3
// speedup vs baseline: 1.7067x; 1.7067x over previous
#include <cuda_runtime.h>
#include <cuda_bf16.h>
#include <cstdint>
#include <math.h>

#define SEQL 2048
#define HID  2048
#define NH   32
#define NKV  8
#define HD   64
#define QKVN 3072
#define GK   2048

// ---------------------------------------------------------------------------
// Scratch (device globals; no allocations allowed)
// ---------------------------------------------------------------------------
__device__ float          g_qkv[SEQL * QKVN];
__device__ float          g_attn[SEQL * NH * HD];
__device__ __nv_bfloat16  g_hid_hi[SEQL * HID];
__device__ __nv_bfloat16  g_hid_lo[SEQL * HID];
__device__ __nv_bfloat16  g_wqkvT_hi[QKVN * GK];
__device__ __nv_bfloat16  g_wqkvT_lo[QKVN * GK];
__device__ __nv_bfloat16  g_woT_hi[HID * GK];
__device__ __nv_bfloat16  g_woT_lo[HID * GK];
__device__ __nv_bfloat16  g_attn_hi[SEQL * HID];
__device__ __nv_bfloat16  g_attn_lo[SEQL * HID];

// ---------------------------------------------------------------------------
// PTX helpers (baseline sm_80+ instructions only — no tcgen05 on sm_103)
// ---------------------------------------------------------------------------
__device__ __forceinline__ uint32_t smem_u32(const void* p) {
    uint32_t a;
    asm("{ .reg .u64 t; cvta.to.shared.u64 t, %1; cvt.u32.u64 %0, t; }" : "=r"(a) : "l"(p));
    return a;
}
#define LDMX4(r, addr) \
    asm volatile("ldmatrix.sync.aligned.m8n8.x4.shared.b16 {%0,%1,%2,%3}, [%4];" \
        : "=r"((r)[0]), "=r"((r)[1]), "=r"((r)[2]), "=r"((r)[3]) : "r"(addr))
#define CP_ASYNC16(dst, src) \
    asm volatile("cp.async.cg.shared.global [%0], [%1], 16;" :: "r"(dst), "l"(src))
#define CP_COMMIT() asm volatile("cp.async.commit_group;")
#define CP_WAIT1()  asm volatile("cp.async.wait_group 1;")
#define CP_WAIT0()  asm volatile("cp.async.wait_group 0;")

__device__ __forceinline__ void mma_bf16(float* d, const uint32_t* a, const uint32_t* b) {
    asm volatile("mma.sync.aligned.m16n8k16.row.col.f32.bf16.bf16.f32 "
        "{%0,%1,%2,%3}, {%4,%5,%6,%7}, {%8,%9}, {%0,%1,%2,%3};"
        : "+f"(d[0]), "+f"(d[1]), "+f"(d[2]), "+f"(d[3])
        : "r"(a[0]), "r"(a[1]), "r"(a[2]), "r"(a[3]), "r"(b[0]), "r"(b[1]));
}

// ---------------------------------------------------------------------------
// Split fp32 -> bf16 hi/lo (elementwise)
// ---------------------------------------------------------------------------
__global__ void split2_kernel(const float* __restrict__ x, __nv_bfloat16* __restrict__ hi,
                              __nv_bfloat16* __restrict__ lo, int n4) {
    int i = blockIdx.x * blockDim.x + threadIdx.x;
    if (i >= n4) return;
    float4 v = ((const float4*)x)[i];
    float a[4] = {v.x, v.y, v.z, v.w};
    __nv_bfloat162 h2[2], l2[2];
#pragma unroll
    for (int p = 0; p < 2; p++) {
        __nv_bfloat16 h0 = __float2bfloat16(a[2 * p]);
        __nv_bfloat16 h1 = __float2bfloat16(a[2 * p + 1]);
        h2[p] = __nv_bfloat162(h0, h1);
        l2[p] = __nv_bfloat162(__float2bfloat16(a[2 * p] - __bfloat162float(h0)),
                               __float2bfloat16(a[2 * p + 1] - __bfloat162float(h1)));
    }
    ((uint2*)hi)[i] = *(uint2*)h2;
    ((uint2*)lo)[i] = *(uint2*)l2;
}

// ---------------------------------------------------------------------------
// Transpose + split: W[K][N] fp32 -> T_hi/T_lo[N][GK] bf16 (rows offset by roff)
// ---------------------------------------------------------------------------
__global__ void tsplit_kernel(const float* __restrict__ W, __nv_bfloat16* __restrict__ Thi,
                              __nv_bfloat16* __restrict__ Tlo, int N, int roff) {
    __shared__ float t[32][33];
    int n0 = blockIdx.x * 32, k0 = blockIdx.y * 32;
    int tx = threadIdx.x, ty = threadIdx.y;
#pragma unroll
    for (int r = 0; r < 4; r++)
        t[ty + 8 * r][tx] = W[(size_t)(k0 + ty + 8 * r) * N + n0 + tx];
    __syncthreads();
#pragma unroll
    for (int r = 0; r < 4; r++) {
        int rr = ty + 8 * r;
        float x = t[tx][rr];
        __nv_bfloat16 h = __float2bfloat16(x);
        size_t o = (size_t)(roff + n0 + rr) * GK + k0 + tx;
        Thi[o] = h;
        Tlo[o] = __float2bfloat16(x - __bfloat162float(h));
    }
}

// ---------------------------------------------------------------------------
// mma.sync split-bf16 GEMM: C[M,N] = A[M,GK] @ B^T (B stored [N][GK])
// 128x128 CTA tile, BK=32, 256 threads = 8 warps (4M x 2N, 32x64 each),
// 2-stage cp.async pipeline. Smem rows padded 32->40 bf16 (80B stride).
// ---------------------------------------------------------------------------
#define TILE_B   10240            // 128 rows * 80B
#define STAGE_B  (4 * TILE_B)     // Ahi, Alo, Bhi, Blo
#define GEMM_SMEM (2 * STAGE_B)   // 81920

__device__ __forceinline__ void gemm_issue(const __nv_bfloat16* const* srcs,
                                           uint32_t sbase, int stage, int k0, int tid) {
#pragma unroll
    for (int t = 0; t < 4; t++) {
        const __nv_bfloat16* s = srcs[t] + k0;
        uint32_t dstb = sbase + stage * STAGE_B + t * TILE_B;
#pragma unroll
        for (int c2 = 0; c2 < 2; c2++) {
            int c = c2 * 256 + tid;
            int row = c >> 2, sub = c & 3;
            CP_ASYNC16(dstb + row * 80 + sub * 16, s + (size_t)row * GK + sub * 8);
        }
    }
    CP_COMMIT();
}

__global__ __launch_bounds__(256, 2) void gemm_mma(
    const __nv_bfloat16* __restrict__ Ahi, const __nv_bfloat16* __restrict__ Alo,
    const __nv_bfloat16* __restrict__ Bhi, const __nv_bfloat16* __restrict__ Blo,
    float* __restrict__ C, int N) {
    extern __shared__ char smem[];
    const uint32_t sbase = smem_u32(smem);
    const int tid = threadIdx.x;
    const int wid = tid >> 5, lane = tid & 31;
    const int wm = wid & 3, wn = wid >> 2;
    const int bm = blockIdx.y, bn = blockIdx.x;

    const __nv_bfloat16* srcs[4] = {
        Ahi + (size_t)bm * 128 * GK, Alo + (size_t)bm * 128 * GK,
        Bhi + (size_t)bn * 128 * GK, Blo + (size_t)bn * 128 * GK};

    float acc[2][8][4];
#pragma unroll
    for (int i = 0; i < 2; i++)
#pragma unroll
        for (int j = 0; j < 8; j++)
#pragma unroll
            for (int k = 0; k < 4; k++) acc[i][j][k] = 0.f;

    const int NIT = GK / 32;
    gemm_issue(srcs, sbase, 0, 0, tid);

    // precomputed ldmatrix lane offsets
    const int a_row = wm * 32 + (lane & 15);
    const int a_koff = (lane >> 4) << 3;                      // 0 or 8
    const int b_row = wn * 64 + (lane & 7) + ((lane >> 4) << 3);
    const int b_koff = ((lane >> 3) & 1) << 3;                // 0 or 8

    for (int i = 0; i < NIT; i++) {
        if (i + 1 < NIT) gemm_issue(srcs, sbase, (i + 1) & 1, (i + 1) * 32, tid);
        if (i + 1 < NIT) { CP_WAIT1(); } else { CP_WAIT0(); }
        __syncthreads();

        uint32_t s_ahi = sbase + (i & 1) * STAGE_B;
        uint32_t s_alo = s_ahi + TILE_B;
        uint32_t s_bhi = s_ahi + 2 * TILE_B;
        uint32_t s_blo = s_ahi + 3 * TILE_B;

#pragma unroll
        for (int ks = 0; ks < 2; ks++) {
            int kc = ks * 16;
            uint32_t ah[2][4], al[2][4];
#pragma unroll
            for (int mf = 0; mf < 2; mf++) {
                uint32_t ro = (a_row + mf * 16) * 80 + (kc + a_koff) * 2;
                LDMX4(ah[mf], s_ahi + ro);
                LDMX4(al[mf], s_alo + ro);
            }
#pragma unroll
            for (int nh = 0; nh < 2; nh++) {
                uint32_t bh[4][2], bl[4][2];
#pragma unroll
                for (int g = 0; g < 2; g++) {
                    uint32_t r[4];
                    uint32_t ro = (b_row + nh * 32 + g * 16) * 80 + (kc + b_koff) * 2;
                    LDMX4(r, s_bhi + ro);
                    bh[g * 2][0] = r[0]; bh[g * 2][1] = r[1];
                    bh[g * 2 + 1][0] = r[2]; bh[g * 2 + 1][1] = r[3];
                    LDMX4(r, s_blo + ro);
                    bl[g * 2][0] = r[0]; bl[g * 2][1] = r[1];
                    bl[g * 2 + 1][0] = r[2]; bl[g * 2 + 1][1] = r[3];
                }
#pragma unroll
                for (int mf = 0; mf < 2; mf++)
#pragma unroll
                    for (int nf = 0; nf < 4; nf++) {
                        float* d = acc[mf][nh * 4 + nf];
                        mma_bf16(d, ah[mf], bh[nf]);
                        mma_bf16(d, ah[mf], bl[nf]);
                        mma_bf16(d, al[mf], bh[nf]);
                    }
            }
        }
        __syncthreads();
    }

    // epilogue
    const int er = lane >> 2, ec = (lane & 3) * 2;
#pragma unroll
    for (int mf = 0; mf < 2; mf++) {
        float* c0 = C + (size_t)(bm * 128 + wm * 32 + mf * 16 + er) * N + bn * 128 + wn * 64 + ec;
#pragma unroll
        for (int nf = 0; nf < 8; nf++) {
            float* cp = c0 + nf * 8;
            cp[0] = acc[mf][nf][0];
            cp[1] = acc[mf][nf][1];
            cp[8 * (size_t)N + 0] = acc[mf][nf][2];
            cp[8 * (size_t)N + 1] = acc[mf][nf][3];
        }
    }
}

// ---------------------------------------------------------------------------
// RoPE on a column slice of g_qkv (row stride QKVN), replicating reference math
// ---------------------------------------------------------------------------
__global__ void rope_kernel(float* __restrict__ x, int nheads, int col_off) {
    int p = blockIdx.x * blockDim.x + threadIdx.x;
    int total = SEQL * nheads * (HD / 2);
    if (p >= total) return;
    int i = p & 31;
    int h = (p >> 5) % nheads;
    int s = p / (nheads * 32);

    float* row = x + (size_t)s * QKVN + col_off + h * HD;
    int d0 = 2 * i, d1 = 2 * i + 1;
    float x0 = row[d0], x1 = row[d1];
    int j0 = d0 & 31, j1 = d1 & 31;

    const float LOGT = 13.122363377404328f;
    float f0 = expf(-(float)j0 * (LOGT / 32.f));
    float f1 = expf(-(float)j1 * (LOGT / 32.f));
    float t = (float)s;
    float s0, c0, s1, c1;
    sincosf(t * f0, &s0, &c0);
    sincosf(t * f1, &s1, &c1);
    row[d0] = x0 * c0 - x1 * s0;
    row[d1] = x1 * c1 + x0 * s1;
}

// ---------------------------------------------------------------------------
// Flash attention, fp32 SIMT, reading fused qkv (row stride QKVN).
// ---------------------------------------------------------------------------
__global__ __launch_bounds__(256) void attn_kernel(const float* __restrict__ QKV,
                                                   float* __restrict__ O) {
    __shared__ float Qs[64][64];
    __shared__ float KPs[64][64];
    __shared__ float Vs[64][64];

    const int h = blockIdx.y;
    const int qb = blockIdx.x;
    const int kvh = h >> 2;
    const int tid = threadIdx.x;
    const int ty = tid >> 4, tx = tid & 15;

    const float* Q = QKV + h * HD;
    const float* K = QKV + 2048 + kvh * HD;
    const float* V = QKV + 2560 + kvh * HD;

#pragma unroll
    for (int r = 0; r < 4; r++) {
        int f = r * 256 + tid;
        int m = f >> 4, c4 = f & 15;
        float4 v4 = *(const float4*)(Q + (size_t)(qb * 64 + m) * QKVN + c4 * 4);
        Qs[c4 * 4 + 0][m] = v4.x;
        Qs[c4 * 4 + 1][m] = v4.y;
        Qs[c4 * 4 + 2][m] = v4.z;
        Qs[c4 * 4 + 3][m] = v4.w;
    }

    float mi[4], li[4], acc[4][4];
#pragma unroll
    for (int i = 0; i < 4; i++) {
        mi[i] = -1e30f; li[i] = 0.f;
#pragma unroll
        for (int j = 0; j < 4; j++) acc[i][j] = 0.f;
    }

    for (int jb = 0; jb <= qb; jb++) {
        __syncthreads();
#pragma unroll
        for (int r = 0; r < 4; r++) {
            int f = r * 256 + tid;
            int n = f >> 4, c4 = f & 15;
            size_t base = (size_t)(jb * 64 + n) * QKVN + c4 * 4;
            float4 kv = *(const float4*)(K + base);
            KPs[c4 * 4 + 0][n] = kv.x;
            KPs[c4 * 4 + 1][n] = kv.y;
            KPs[c4 * 4 + 2][n] = kv.z;
            KPs[c4 * 4 + 3][n] = kv.w;
            *(float4*)&Vs[n][c4 * 4] = *(const float4*)(V + base);
        }
        __syncthreads();

        float s[4][4];
#pragma unroll
        for (int i = 0; i < 4; i++)
#pragma unroll
            for (int j = 0; j < 4; j++) s[i][j] = 0.f;
#pragma unroll
        for (int d = 0; d < 64; d++) {
            float a[4], b[4];
            *(float4*)a = *(const float4*)&Qs[d][ty * 4];
            *(float4*)b = *(const float4*)&KPs[d][tx * 4];
#pragma unroll
            for (int i = 0; i < 4; i++)
#pragma unroll
                for (int j = 0; j < 4; j++) s[i][j] = fmaf(a[i], b[j], s[i][j]);
        }
        __syncthreads();

        const float scale = 0.125f;
        int row0 = qb * 64 + ty * 4;
        int col0 = jb * 64 + tx * 4;
#pragma unroll
        for (int i = 0; i < 4; i++)
#pragma unroll
            for (int j = 0; j < 4; j++)
                s[i][j] = s[i][j] * scale + ((col0 + j > row0 + i) ? -1e9f : 0.f);

#pragma unroll
        for (int i = 0; i < 4; i++) {
            float rm = fmaxf(fmaxf(s[i][0], s[i][1]), fmaxf(s[i][2], s[i][3]));
#pragma unroll
            for (int off = 8; off; off >>= 1)
                rm = fmaxf(rm, __shfl_xor_sync(0xffffffffu, rm, off));
            float nm = fmaxf(mi[i], rm);
            float alpha = expf(mi[i] - nm);
            mi[i] = nm;
            float rs = 0.f;
#pragma unroll
            for (int j = 0; j < 4; j++) { s[i][j] = expf(s[i][j] - nm); rs += s[i][j]; }
#pragma unroll
            for (int off = 8; off; off >>= 1)
                rs += __shfl_xor_sync(0xffffffffu, rs, off);
            li[i] = li[i] * alpha + rs;
#pragma unroll
            for (int j = 0; j < 4; j++) acc[i][j] *= alpha;
        }

#pragma unroll
        for (int j = 0; j < 4; j++)
            *(float4*)&KPs[tx * 4 + j][ty * 4] =
                make_float4(s[0][j], s[1][j], s[2][j], s[3][j]);
        __syncthreads();

#pragma unroll
        for (int c = 0; c < 64; c++) {
            float a[4], b[4];
            *(float4*)a = *(const float4*)&KPs[c][ty * 4];
            *(float4*)b = *(const float4*)&Vs[c][tx * 4];
#pragma unroll
            for (int i = 0; i < 4; i++)
#pragma unroll
                for (int j = 0; j < 4; j++) acc[i][j] = fmaf(a[i], b[j], acc[i][j]);
        }
    }

#pragma unroll
    for (int i = 0; i < 4; i++) {
        float inv = 1.0f / li[i];
        *(float4*)(O + (size_t)(qb * 64 + ty * 4 + i) * (NH * HD) + h * HD + tx * 4) =
            make_float4(acc[i][0] * inv, acc[i][1] * inv, acc[i][2] * inv, acc[i][3] * inv);
    }
}

// ---------------------------------------------------------------------------
extern "C" void kernel_launch(void* const* d_in, const int* in_sizes, int n_in,
                              void* d_out, int out_size) {
    const float* hidden = (const float*)d_in[0];
    const float* Wq = (const float*)d_in[2];
    const float* Wk = (const float*)d_in[3];
    const float* Wv = (const float*)d_in[4];
    const float* Wo = (const float*)d_in[5];
    float* out = (float*)d_out;

    float *qkv, *attn;
    __nv_bfloat16 *hh, *hl, *wqh, *wql, *woh, *wol, *ah, *al;
    cudaGetSymbolAddress((void**)&qkv, g_qkv);
    cudaGetSymbolAddress((void**)&attn, g_attn);
    cudaGetSymbolAddress((void**)&hh, g_hid_hi);
    cudaGetSymbolAddress((void**)&hl, g_hid_lo);
    cudaGetSymbolAddress((void**)&wqh, g_wqkvT_hi);
    cudaGetSymbolAddress((void**)&wql, g_wqkvT_lo);
    cudaGetSymbolAddress((void**)&woh, g_woT_hi);
    cudaGetSymbolAddress((void**)&wol, g_woT_lo);
    cudaGetSymbolAddress((void**)&ah, g_attn_hi);
    cudaGetSymbolAddress((void**)&al, g_attn_lo);

    cudaFuncSetAttribute(gemm_mma, cudaFuncAttributeMaxDynamicSharedMemorySize, GEMM_SMEM);

    // 1) split hidden, transpose+split weights
    split2_kernel<<<(SEQL * HID / 4 + 255) / 256, 256>>>(hidden, hh, hl, SEQL * HID / 4);
    tsplit_kernel<<<dim3(2048 / 32, GK / 32), dim3(32, 8)>>>(Wq, wqh, wql, 2048, 0);
    tsplit_kernel<<<dim3(512 / 32, GK / 32), dim3(32, 8)>>>(Wk, wqh, wql, 512, 2048);
    tsplit_kernel<<<dim3(512 / 32, GK / 32), dim3(32, 8)>>>(Wv, wqh, wql, 512, 2560);
    tsplit_kernel<<<dim3(2048 / 32, GK / 32), dim3(32, 8)>>>(Wo, woh, wol, 2048, 0);

    // 2) fused QKV projection (mma.sync split-bf16)
    gemm_mma<<<dim3(QKVN / 128, SEQL / 128), 256, GEMM_SMEM>>>(hh, hl, wqh, wql, qkv, QKVN);

    // 3) RoPE on q and k slices
    rope_kernel<<<(SEQL * NH * 32 + 255) / 256, 256>>>(qkv, NH, 0);
    rope_kernel<<<(SEQL * NKV * 32 + 255) / 256, 256>>>(qkv, NKV, 2048);

    // 4) causal GQA flash attention (fp32 SIMT)
    attn_kernel<<<dim3(SEQL / 64, NH), 256>>>(qkv, attn);

    // 5) split attention output, O-projection
    split2_kernel<<<(SEQL * HID / 4 + 255) / 256, 256>>>(attn, ah, al, SEQL * HID / 4);
    gemm_mma<<<dim3(HID / 128, SEQL / 128), 256, GEMM_SMEM>>>(ah, al, woh, wol, out, HID);
}

// round 4
// speedup vs baseline: 3.5932x; 2.1053x over previous
#include <cuda_runtime.h>
#include <cuda_bf16.h>
#include <cstdint>
#include <math.h>

#define SEQL 2048
#define HID  2048
#define NH   32
#define NKV  8
#define HD   64
#define QKVN 3072
#define GK   2048

// ---------------------------------------------------------------------------
// Scratch (device globals; no allocations allowed)
// ---------------------------------------------------------------------------
__device__ float          g_qkv[SEQL * QKVN];          // fp32 QKV (pre-rope)
__device__ __nv_bfloat16  g_hid_hi[SEQL * HID];
__device__ __nv_bfloat16  g_hid_lo[SEQL * HID];
__device__ __nv_bfloat16  g_wqkvT_hi[QKVN * GK];
__device__ __nv_bfloat16  g_wqkvT_lo[QKVN * GK];
__device__ __nv_bfloat16  g_woT_hi[HID * GK];
__device__ __nv_bfloat16  g_woT_lo[HID * GK];
__device__ __nv_bfloat16  g_attn_hi[SEQL * HID];       // attention out (split)
__device__ __nv_bfloat16  g_attn_lo[SEQL * HID];
__device__ __nv_bfloat16  g_qh[SEQL * NH * HD];        // rope'd q split [s][2048]
__device__ __nv_bfloat16  g_ql[SEQL * NH * HD];
__device__ __nv_bfloat16  g_kh[SEQL * NKV * HD];       // rope'd k split [s][512]
__device__ __nv_bfloat16  g_kl[SEQL * NKV * HD];
__device__ __nv_bfloat16  g_vh[SEQL * NKV * HD];       // v split [s][512]
__device__ __nv_bfloat16  g_vl[SEQL * NKV * HD];

// ---------------------------------------------------------------------------
// PTX helpers (baseline sm_80+ only)
// ---------------------------------------------------------------------------
__device__ __forceinline__ uint32_t smem_u32(const void* p) {
    uint32_t a;
    asm("{ .reg .u64 t; cvta.to.shared.u64 t, %1; cvt.u32.u64 %0, t; }" : "=r"(a) : "l"(p));
    return a;
}
#define LDMX4(r, addr) \
    asm volatile("ldmatrix.sync.aligned.m8n8.x4.shared.b16 {%0,%1,%2,%3}, [%4];" \
        : "=r"((r)[0]), "=r"((r)[1]), "=r"((r)[2]), "=r"((r)[3]) : "r"(addr))
#define LDMX4T(r, addr) \
    asm volatile("ldmatrix.sync.aligned.m8n8.x4.trans.shared.b16 {%0,%1,%2,%3}, [%4];" \
        : "=r"((r)[0]), "=r"((r)[1]), "=r"((r)[2]), "=r"((r)[3]) : "r"(addr))
#define CP_ASYNC16(dst, src) \
    asm volatile("cp.async.cg.shared.global [%0], [%1], 16;" :: "r"(dst), "l"(src))
#define CP_COMMIT() asm volatile("cp.async.commit_group;")
#define CP_WAIT1()  asm volatile("cp.async.wait_group 1;")
#define CP_WAIT0()  asm volatile("cp.async.wait_group 0;")

__device__ __forceinline__ void mma_bf16(float* d, const uint32_t* a, const uint32_t* b) {
    asm volatile("mma.sync.aligned.m16n8k16.row.col.f32.bf16.bf16.f32 "
        "{%0,%1,%2,%3}, {%4,%5,%6,%7}, {%8,%9}, {%0,%1,%2,%3};"
        : "+f"(d[0]), "+f"(d[1]), "+f"(d[2]), "+f"(d[3])
        : "r"(a[0]), "r"(a[1]), "r"(a[2]), "r"(a[3]), "r"(b[0]), "r"(b[1]));
}

__device__ __forceinline__ uint32_t pack_bf16(float x, float y) {
    __nv_bfloat162 t;
    t.x = __float2bfloat16(x);
    t.y = __float2bfloat16(y);
    return *(uint32_t*)&t;
}
__device__ __forceinline__ void split_pack(float x, float y, uint32_t& hi, uint32_t& lo) {
    __nv_bfloat16 hx = __float2bfloat16(x), hy = __float2bfloat16(y);
    __nv_bfloat162 h2; h2.x = hx; h2.y = hy;
    __nv_bfloat162 l2;
    l2.x = __float2bfloat16(x - __bfloat162float(hx));
    l2.y = __float2bfloat16(y - __bfloat162float(hy));
    hi = *(uint32_t*)&h2;
    lo = *(uint32_t*)&l2;
}

// ---------------------------------------------------------------------------
// Split fp32 -> bf16 hi/lo (elementwise)
// ---------------------------------------------------------------------------
__global__ void split2_kernel(const float* __restrict__ x, __nv_bfloat16* __restrict__ hi,
                              __nv_bfloat16* __restrict__ lo, int n4) {
    int i = blockIdx.x * blockDim.x + threadIdx.x;
    if (i >= n4) return;
    float4 v = ((const float4*)x)[i];
    uint32_t h0, l0, h1, l1;
    split_pack(v.x, v.y, h0, l0);
    split_pack(v.z, v.w, h1, l1);
    ((uint2*)hi)[i] = make_uint2(h0, h1);
    ((uint2*)lo)[i] = make_uint2(l0, l1);
}

// ---------------------------------------------------------------------------
// Transpose + split: W[K][N] fp32 -> T_hi/T_lo[N][GK] bf16 (rows offset by roff)
// ---------------------------------------------------------------------------
__global__ void tsplit_kernel(const float* __restrict__ W, __nv_bfloat16* __restrict__ Thi,
                              __nv_bfloat16* __restrict__ Tlo, int N, int roff) {
    __shared__ float t[32][33];
    int n0 = blockIdx.x * 32, k0 = blockIdx.y * 32;
    int tx = threadIdx.x, ty = threadIdx.y;
#pragma unroll
    for (int r = 0; r < 4; r++)
        t[ty + 8 * r][tx] = W[(size_t)(k0 + ty + 8 * r) * N + n0 + tx];
    __syncthreads();
#pragma unroll
    for (int r = 0; r < 4; r++) {
        int rr = ty + 8 * r;
        float x = t[tx][rr];
        __nv_bfloat16 h = __float2bfloat16(x);
        size_t o = (size_t)(roff + n0 + rr) * GK + k0 + tx;
        Thi[o] = h;
        Tlo[o] = __float2bfloat16(x - __bfloat162float(h));
    }
}

// ---------------------------------------------------------------------------
// mma.sync split-bf16 GEMM (unchanged from R3)
// ---------------------------------------------------------------------------
#define TILE_B   10240
#define STAGE_B  (4 * TILE_B)
#define GEMM_SMEM (2 * STAGE_B)

__device__ __forceinline__ void gemm_issue(const __nv_bfloat16* const* srcs,
                                           uint32_t sbase, int stage, int k0, int tid) {
#pragma unroll
    for (int t = 0; t < 4; t++) {
        const __nv_bfloat16* s = srcs[t] + k0;
        uint32_t dstb = sbase + stage * STAGE_B + t * TILE_B;
#pragma unroll
        for (int c2 = 0; c2 < 2; c2++) {
            int c = c2 * 256 + tid;
            int row = c >> 2, sub = c & 3;
            CP_ASYNC16(dstb + row * 80 + sub * 16, s + (size_t)row * GK + sub * 8);
        }
    }
    CP_COMMIT();
}

__global__ __launch_bounds__(256, 2) void gemm_mma(
    const __nv_bfloat16* __restrict__ Ahi, const __nv_bfloat16* __restrict__ Alo,
    const __nv_bfloat16* __restrict__ Bhi, const __nv_bfloat16* __restrict__ Blo,
    float* __restrict__ C, int N) {
    extern __shared__ char smem[];
    const uint32_t sbase = smem_u32(smem);
    const int tid = threadIdx.x;
    const int wid = tid >> 5, lane = tid & 31;
    const int wm = wid & 3, wn = wid >> 2;
    const int bm = blockIdx.y, bn = blockIdx.x;

    const __nv_bfloat16* srcs[4] = {
        Ahi + (size_t)bm * 128 * GK, Alo + (size_t)bm * 128 * GK,
        Bhi + (size_t)bn * 128 * GK, Blo + (size_t)bn * 128 * GK};

    float acc[2][8][4];
#pragma unroll
    for (int i = 0; i < 2; i++)
#pragma unroll
        for (int j = 0; j < 8; j++)
#pragma unroll
            for (int k = 0; k < 4; k++) acc[i][j][k] = 0.f;

    const int NIT = GK / 32;
    gemm_issue(srcs, sbase, 0, 0, tid);

    const int a_row = wm * 32 + (lane & 15);
    const int a_koff = (lane >> 4) << 3;
    const int b_row = wn * 64 + (lane & 7) + ((lane >> 4) << 3);
    const int b_koff = ((lane >> 3) & 1) << 3;

    for (int i = 0; i < NIT; i++) {
        if (i + 1 < NIT) gemm_issue(srcs, sbase, (i + 1) & 1, (i + 1) * 32, tid);
        if (i + 1 < NIT) { CP_WAIT1(); } else { CP_WAIT0(); }
        __syncthreads();

        uint32_t s_ahi = sbase + (i & 1) * STAGE_B;
        uint32_t s_alo = s_ahi + TILE_B;
        uint32_t s_bhi = s_ahi + 2 * TILE_B;
        uint32_t s_blo = s_ahi + 3 * TILE_B;

#pragma unroll
        for (int ks = 0; ks < 2; ks++) {
            int kc = ks * 16;
            uint32_t ah[2][4], al[2][4];
#pragma unroll
            for (int mf = 0; mf < 2; mf++) {
                uint32_t ro = (a_row + mf * 16) * 80 + (kc + a_koff) * 2;
                LDMX4(ah[mf], s_ahi + ro);
                LDMX4(al[mf], s_alo + ro);
            }
#pragma unroll
            for (int nh = 0; nh < 2; nh++) {
                uint32_t bh[4][2], bl[4][2];
#pragma unroll
                for (int g = 0; g < 2; g++) {
                    uint32_t r[4];
                    uint32_t ro = (b_row + nh * 32 + g * 16) * 80 + (kc + b_koff) * 2;
                    LDMX4(r, s_bhi + ro);
                    bh[g * 2][0] = r[0]; bh[g * 2][1] = r[1];
                    bh[g * 2 + 1][0] = r[2]; bh[g * 2 + 1][1] = r[3];
                    LDMX4(r, s_blo + ro);
                    bl[g * 2][0] = r[0]; bl[g * 2][1] = r[1];
                    bl[g * 2 + 1][0] = r[2]; bl[g * 2 + 1][1] = r[3];
                }
#pragma unroll
                for (int mf = 0; mf < 2; mf++)
#pragma unroll
                    for (int nf = 0; nf < 4; nf++) {
                        float* d = acc[mf][nh * 4 + nf];
                        mma_bf16(d, ah[mf], bh[nf]);
                        mma_bf16(d, ah[mf], bl[nf]);
                        mma_bf16(d, al[mf], bh[nf]);
                    }
            }
        }
        __syncthreads();
    }

    const int er = lane >> 2, ec = (lane & 3) * 2;
#pragma unroll
    for (int mf = 0; mf < 2; mf++) {
        float* c0 = C + (size_t)(bm * 128 + wm * 32 + mf * 16 + er) * N + bn * 128 + wn * 64 + ec;
#pragma unroll
        for (int nf = 0; nf < 8; nf++) {
            float* cp = c0 + nf * 8;
            cp[0] = acc[mf][nf][0];
            cp[1] = acc[mf][nf][1];
            cp[8 * (size_t)N + 0] = acc[mf][nf][2];
            cp[8 * (size_t)N + 1] = acc[mf][nf][3];
        }
    }
}

// ---------------------------------------------------------------------------
// Fused RoPE + bf16-split of q/k/v out of fp32 qkv.
// ---------------------------------------------------------------------------
__global__ void rope_split_kernel(const float* __restrict__ qkv) {
    int p = blockIdx.x * blockDim.x + threadIdx.x;
    if (p >= SEQL * 1536) return;
    int s = p / 1536, col = (p % 1536) * 2;
    const float* row = qkv + (size_t)s * QKVN;
    float x0 = row[col], x1 = row[col + 1];
    float y0, y1;
    if (col < 2560) {   // q + k get rope
        int j0 = col & 31;
        const float LOGT = 13.122363377404328f;   // ln(500000)
        float f0 = expf(-(float)j0 * (LOGT / 32.f));
        float f1 = expf(-(float)(j0 + 1) * (LOGT / 32.f));
        float t = (float)s;
        float s0, c0, s1, c1;
        sincosf(t * f0, &s0, &c0);
        sincosf(t * f1, &s1, &c1);
        y0 = x0 * c0 - x1 * s0;
        y1 = x1 * c1 + x0 * s1;
    } else { y0 = x0; y1 = x1; }
    uint32_t hw, lw;
    split_pack(y0, y1, hw, lw);
    if (col < 2048) {
        int idx = (s * 2048 + col) >> 1;
        ((uint32_t*)g_qh)[idx] = hw;
        ((uint32_t*)g_ql)[idx] = lw;
    } else if (col < 2560) {
        int idx = (s * 512 + col - 2048) >> 1;
        ((uint32_t*)g_kh)[idx] = hw;
        ((uint32_t*)g_kl)[idx] = lw;
    } else {
        int idx = (s * 512 + col - 2560) >> 1;
        ((uint32_t*)g_vh)[idx] = hw;
        ((uint32_t*)g_vl)[idx] = lw;
    }
}

// ---------------------------------------------------------------------------
// Tensor-core flash attention (split-bf16), 64 q-rows/CTA, 128 threads.
// Smem: Qh|Ql (8KB each) + 2 stages of Kh|Kl|Vh|Vl (8KB each). XOR swizzle.
// ---------------------------------------------------------------------------
#define AT_SMEM (16384 + 2 * 32768)
#define SWZ(row, cb) ((uint32_t)((row) * 128 + ((cb) ^ (((row) & 7) << 4))))

__device__ __forceinline__ void attn_issue_kv(uint32_t base, int jb, int kvh, int tid) {
#pragma unroll
    for (int it = 0; it < 16; it++) {
        const int arr = it >> 2;
        const __nv_bfloat16* p = (arr == 0) ? g_kh : (arr == 1) ? g_kl
                               : (arr == 2) ? g_vh : g_vl;
        int row = (it & 3) * 16 + (tid >> 3);
        int sub = tid & 7;
        size_t off = (size_t)(jb * 64 + row) * 512 + kvh * 64 + sub * 8;
        CP_ASYNC16(base + arr * 8192 + SWZ(row, sub * 16), p + off);
    }
    CP_COMMIT();
}

__global__ __launch_bounds__(128) void attn_mma(void) {
    extern __shared__ char smem[];
    const uint32_t sb = smem_u32(smem);
    const int tid = threadIdx.x, wid = tid >> 5, lane = tid & 31;
    const int qb = gridDim.x - 1 - blockIdx.x;   // heavy blocks first
    const int h = blockIdx.y, kvh = h >> 2;
    const uint32_t sKV = sb + 16384;

    // issue Q (into its own region) + first KV stage as group 0
#pragma unroll
    for (int it = 0; it < 8; it++) {
        const int arr = it >> 2;
        const __nv_bfloat16* p = arr ? g_ql : g_qh;
        int row = (it & 3) * 16 + (tid >> 3);
        int sub = tid & 7;
        size_t off = (size_t)(qb * 64 + row) * 2048 + h * 64 + sub * 8;
        CP_ASYNC16(sb + arr * 8192 + SWZ(row, sub * 16), p + off);
    }
    attn_issue_kv(sKV, 0, kvh, tid);            // commits group 0 (with Q)
    if (qb >= 1) attn_issue_kv(sKV + 32768, 1, kvh, tid);  // group 1

    float m0 = -1e30f, m1 = -1e30f, l0 = 0.f, l1 = 0.f;
    float o[8][4];
#pragma unroll
    for (int j = 0; j < 8; j++)
#pragma unroll
        for (int k = 0; k < 4; k++) o[j][k] = 0.f;

    uint32_t qfh[4][4], qfl[4][4];

    // ldmatrix lane addressing
    const int a_row = wid * 16 + (lane & 15);
    const int a_koff = (lane >> 4) << 3;
    const int b_row0 = (lane & 7) + ((lane >> 4) << 3);
    const int b_koff = ((lane >> 3) & 1) << 3;
    const int v_row0 = lane & 15;
    const int v_coff = (lane >> 4) << 3;

    for (int jb = 0; jb <= qb; jb++) {
        if (jb == 0) {
            if (qb >= 1) { CP_WAIT1(); } else { CP_WAIT0(); }
        } else {
            if (jb + 1 <= qb) {
                attn_issue_kv(sKV + ((jb + 1) & 1) * 32768, jb + 1, kvh, tid);
                CP_WAIT1();
            } else { CP_WAIT0(); }
        }
        __syncthreads();

        if (jb == 0) {   // Q frags (once)
#pragma unroll
            for (int ks = 0; ks < 4; ks++) {
                uint32_t ro = SWZ(a_row, (ks * 16 + a_koff) * 2);
                LDMX4(qfh[ks], sb + ro);
                LDMX4(qfl[ks], sb + 8192 + ro);
            }
        }

        const uint32_t st = sKV + (jb & 1) * 32768;

        // ---- S = Q K^T (split) ----
        float s[8][4];
#pragma unroll
        for (int j = 0; j < 8; j++)
#pragma unroll
            for (int k = 0; k < 4; k++) s[j][k] = 0.f;
#pragma unroll
        for (int ks = 0; ks < 4; ks++) {
#pragma unroll
            for (int nb = 0; nb < 4; nb++) {
                uint32_t kbh[4], kbl[4];
                uint32_t ro = SWZ(nb * 16 + b_row0, (ks * 16 + b_koff) * 2);
                LDMX4(kbh, st + ro);
                LDMX4(kbl, st + 8192 + ro);
                mma_bf16(s[2 * nb], qfh[ks], kbh);
                mma_bf16(s[2 * nb], qfh[ks], kbl);
                mma_bf16(s[2 * nb], qfl[ks], kbh);
                mma_bf16(s[2 * nb + 1], qfh[ks], kbh + 2);
                mma_bf16(s[2 * nb + 1], qfh[ks], kbl + 2);
                mma_bf16(s[2 * nb + 1], qfl[ks], kbh + 2);
            }
        }

        // ---- scale + causal mask ----
        const float scale = 0.125f;
        if (jb == qb) {
            int rp0 = wid * 16 + (lane >> 2);
#pragma unroll
            for (int j = 0; j < 8; j++) {
                int cp = j * 8 + (lane & 3) * 2;
                s[j][0] = s[j][0] * scale + ((cp > rp0) ? -1e9f : 0.f);
                s[j][1] = s[j][1] * scale + ((cp + 1 > rp0) ? -1e9f : 0.f);
                s[j][2] = s[j][2] * scale + ((cp > rp0 + 8) ? -1e9f : 0.f);
                s[j][3] = s[j][3] * scale + ((cp + 1 > rp0 + 8) ? -1e9f : 0.f);
            }
        } else {
#pragma unroll
            for (int j = 0; j < 8; j++)
#pragma unroll
                for (int k = 0; k < 4; k++) s[j][k] *= scale;
        }

        // ---- online softmax ----
        float mx0 = -1e30f, mx1 = -1e30f;
#pragma unroll
        for (int j = 0; j < 8; j++) {
            mx0 = fmaxf(mx0, fmaxf(s[j][0], s[j][1]));
            mx1 = fmaxf(mx1, fmaxf(s[j][2], s[j][3]));
        }
        mx0 = fmaxf(mx0, __shfl_xor_sync(0xffffffffu, mx0, 1));
        mx0 = fmaxf(mx0, __shfl_xor_sync(0xffffffffu, mx0, 2));
        mx1 = fmaxf(mx1, __shfl_xor_sync(0xffffffffu, mx1, 1));
        mx1 = fmaxf(mx1, __shfl_xor_sync(0xffffffffu, mx1, 2));
        float nm0 = fmaxf(m0, mx0), nm1 = fmaxf(m1, mx1);
        float al0 = __expf(m0 - nm0), al1 = __expf(m1 - nm1);
        m0 = nm0; m1 = nm1;
        float rs0 = 0.f, rs1 = 0.f;
#pragma unroll
        for (int j = 0; j < 8; j++) {
            s[j][0] = __expf(s[j][0] - nm0);
            s[j][1] = __expf(s[j][1] - nm0);
            s[j][2] = __expf(s[j][2] - nm1);
            s[j][3] = __expf(s[j][3] - nm1);
            rs0 += s[j][0] + s[j][1];
            rs1 += s[j][2] + s[j][3];
        }
        l0 = l0 * al0 + rs0;
        l1 = l1 * al1 + rs1;
#pragma unroll
        for (int j = 0; j < 8; j++) {
            o[j][0] *= al0; o[j][1] *= al0;
            o[j][2] *= al1; o[j][3] *= al1;
        }

        // ---- O += P V (split) ----
#pragma unroll
        for (int ks = 0; ks < 4; ks++) {
            uint32_t pah[4], pal[4];
            split_pack(s[2 * ks][0], s[2 * ks][1], pah[0], pal[0]);
            split_pack(s[2 * ks][2], s[2 * ks][3], pah[1], pal[1]);
            split_pack(s[2 * ks + 1][0], s[2 * ks + 1][1], pah[2], pal[2]);
            split_pack(s[2 * ks + 1][2], s[2 * ks + 1][3], pah[3], pal[3]);
#pragma unroll
            for (int db = 0; db < 4; db++) {
                uint32_t vbh[4], vbl[4];
                uint32_t ro = SWZ(ks * 16 + v_row0, (db * 16 + v_coff) * 2);
                LDMX4T(vbh, st + 16384 + ro);
                LDMX4T(vbl, st + 24576 + ro);
                mma_bf16(o[2 * db], pah, vbh);
                mma_bf16(o[2 * db], pah, vbl);
                mma_bf16(o[2 * db], pal, vbh);
                mma_bf16(o[2 * db + 1], pah, vbh + 2);
                mma_bf16(o[2 * db + 1], pah, vbl + 2);
                mma_bf16(o[2 * db + 1], pal, vbh + 2);
            }
        }
        __syncthreads();
    }

    // ---- epilogue: finish l, normalize, split-write ----
    l0 += __shfl_xor_sync(0xffffffffu, l0, 1);
    l0 += __shfl_xor_sync(0xffffffffu, l0, 2);
    l1 += __shfl_xor_sync(0xffffffffu, l1, 1);
    l1 += __shfl_xor_sync(0xffffffffu, l1, 2);
    float inv0 = 1.f / l0, inv1 = 1.f / l1;
    int r0 = qb * 64 + wid * 16 + (lane >> 2);
    int cb = h * 64 + (lane & 3) * 2;
#pragma unroll
    for (int j = 0; j < 8; j++) {
        int c = cb + j * 8;
        uint32_t hw, lw;
        split_pack(o[j][0] * inv0, o[j][1] * inv0, hw, lw);
        ((uint32_t*)g_attn_hi)[(r0 * 2048 + c) >> 1] = hw;
        ((uint32_t*)g_attn_lo)[(r0 * 2048 + c) >> 1] = lw;
        split_pack(o[j][2] * inv1, o[j][3] * inv1, hw, lw);
        ((uint32_t*)g_attn_hi)[((r0 + 8) * 2048 + c) >> 1] = hw;
        ((uint32_t*)g_attn_lo)[((r0 + 8) * 2048 + c) >> 1] = lw;
    }
}

// ---------------------------------------------------------------------------
extern "C" void kernel_launch(void* const* d_in, const int* in_sizes, int n_in,
                              void* d_out, int out_size) {
    const float* hidden = (const float*)d_in[0];
    const float* Wq = (const float*)d_in[2];
    const float* Wk = (const float*)d_in[3];
    const float* Wv = (const float*)d_in[4];
    const float* Wo = (const float*)d_in[5];
    float* out = (float*)d_out;

    float* qkv;
    __nv_bfloat16 *hh, *hl, *wqh, *wql, *woh, *wol, *ah, *al;
    cudaGetSymbolAddress((void**)&qkv, g_qkv);
    cudaGetSymbolAddress((void**)&hh, g_hid_hi);
    cudaGetSymbolAddress((void**)&hl, g_hid_lo);
    cudaGetSymbolAddress((void**)&wqh, g_wqkvT_hi);
    cudaGetSymbolAddress((void**)&wql, g_wqkvT_lo);
    cudaGetSymbolAddress((void**)&woh, g_woT_hi);
    cudaGetSymbolAddress((void**)&wol, g_woT_lo);
    cudaGetSymbolAddress((void**)&ah, g_attn_hi);
    cudaGetSymbolAddress((void**)&al, g_attn_lo);

    cudaFuncSetAttribute(gemm_mma, cudaFuncAttributeMaxDynamicSharedMemorySize, GEMM_SMEM);
    cudaFuncSetAttribute(attn_mma, cudaFuncAttributeMaxDynamicSharedMemorySize, AT_SMEM);

    // 1) operand prep
    split2_kernel<<<(SEQL * HID / 4 + 255) / 256, 256>>>(hidden, hh, hl, SEQL * HID / 4);
    tsplit_kernel<<<dim3(2048 / 32, GK / 32), dim3(32, 8)>>>(Wq, wqh, wql, 2048, 0);
    tsplit_kernel<<<dim3(512 / 32, GK / 32), dim3(32, 8)>>>(Wk, wqh, wql, 512, 2048);
    tsplit_kernel<<<dim3(512 / 32, GK / 32), dim3(32, 8)>>>(Wv, wqh, wql, 512, 2560);
    tsplit_kernel<<<dim3(2048 / 32, GK / 32), dim3(32, 8)>>>(Wo, woh, wol, 2048, 0);

    // 2) fused QKV projection
    gemm_mma<<<dim3(QKVN / 128, SEQL / 128), 256, GEMM_SMEM>>>(hh, hl, wqh, wql, qkv, QKVN);

    // 3) RoPE + split q/k/v
    rope_split_kernel<<<(SEQL * 1536 + 255) / 256, 256>>>(qkv);

    // 4) tensor-core causal GQA flash attention
    attn_mma<<<dim3(SEQL / 64, NH), 128, AT_SMEM>>>();

    // 5) O-projection
    gemm_mma<<<dim3(HID / 128, SEQL / 128), 256, GEMM_SMEM>>>(ah, al, woh, wol, out, HID);
}